// round 5
// baseline (speedup 1.0000x reference)
#include <cuda_runtime.h>

#define NN 100000
#define EE 1600000
#define IN_D 128
#define HID_D 64
#define OUT_D 128

// ---------------- device scratch (globals: no allocation allowed) ----------
__device__ int   g_is64;              // 1 if edge_index is int64, 0 if int32
__device__ float g_deg [NN];
__device__ float g_dinv[NN];
__device__ int   g_cnt [NN];          // in-degree histogram (edges only)
__device__ int   g_rowstart[NN + 1];  // CSR offsets by destination
__device__ int   g_cursor[NN];        // fill cursors
__device__ int   g_src[EE];           // CSR: source node per edge
__device__ float g_wt [EE];           // CSR: normalized weight per edge
__device__ __align__(16) float g_h1  [(size_t)NN * HID_D];   // x @ W1
__device__ __align__(16) float g_agg1[(size_t)NN * HID_D];   // propagated layer-1
__device__ __align__(16) float g_h2  [(size_t)NN * OUT_D];   // relu(agg1+b1) @ W2

// ---------------- edge dtype autodetect -------------------------------------
// int64 little-endian: words 2e = low half (value < 2^31), 2e+1 = high = 0.
// int32: odd words are random indices in [0, NN) -> 128 consecutive zeros is
// impossible. Reads stay within the first 256 words (< 3.2M either way).
__global__ void k_detect(const unsigned int* __restrict__ ew) {
    int all_zero = 1;
    for (int e = 0; e < 128; e++)
        if (ew[2 * e + 1] != 0u) { all_zero = 0; break; }
    g_is64 = all_zero;
}

__device__ __forceinline__ int edge_row(const void* ei, int e) {
    if (g_is64) return (int)((const long long*)ei)[e];
    return ((const int*)ei)[e];
}
__device__ __forceinline__ int edge_col(const void* ei, int e) {
    if (g_is64) return (int)((const long long*)ei)[(size_t)EE + e];
    return ((const int*)ei)[(size_t)EE + e];
}

// ---------------- degree / histogram ----------------------------------------
__global__ void k_init() {
    int i = blockIdx.x * blockDim.x + threadIdx.x;
    if (i < NN) { g_deg[i] = 1.0f; g_cnt[i] = 0; }   // self-loop weight 1
}

__global__ void k_deg_cnt(const void* __restrict__ ei, const float* __restrict__ w) {
    int e = blockIdx.x * blockDim.x + threadIdx.x;
    if (e < EE) {
        int c = edge_col(ei, e);                     // col = destination
        atomicAdd(&g_deg[c], w[e]);                  // scalar float atomic
        atomicAdd(&g_cnt[c], 1);                     // scalar int atomic
    }
}

__global__ void k_dinv() {
    int i = blockIdx.x * blockDim.x + threadIdx.x;
    if (i < NN) g_dinv[i] = rsqrtf(g_deg[i]);        // deg >= 1 always
}

// ---------------- single-block chunked exclusive scan -----------------------
__global__ void k_scan() {                           // <<<1, 1024>>>
    const int T = 1024;
    int t = threadIdx.x;
    int chunk = (NN + T - 1) / T;                    // 98
    int lo = t * chunk;
    int hi = lo + chunk; if (hi > NN) hi = NN;

    int s = 0;
    for (int i = lo; i < hi; i++) s += g_cnt[i];

    __shared__ int ps[T];
    ps[t] = s;
    __syncthreads();
    for (int off = 1; off < T; off <<= 1) {          // inclusive scan
        int v = (t >= off) ? ps[t - off] : 0;
        __syncthreads();
        ps[t] += v;
        __syncthreads();
    }
    int base = (t > 0) ? ps[t - 1] : 0;              // exclusive base for chunk
    for (int i = lo; i < hi; i++) {
        int c = g_cnt[i];
        g_rowstart[i] = base;
        g_cursor[i]   = base;
        base += c;
    }
    if (t == T - 1) g_rowstart[NN] = ps[T - 1];      // == EE
}

// ---------------- CSR fill (dest-sorted) -------------------------------------
__global__ void k_fill(const void* __restrict__ ei, const float* __restrict__ w) {
    int e = blockIdx.x * blockDim.x + threadIdx.x;
    if (e >= EE) return;
    int r = edge_row(ei, e);
    int c = edge_col(ei, e);
    float nm = g_dinv[r] * w[e] * g_dinv[c];
    int pos = atomicAdd(&g_cursor[c], 1);            // scalar int atomic
    g_src[pos] = r;
    g_wt [pos] = nm;
}

// ---------------- register-tiled SGEMM: C[n,J] = f(A[n,K]) @ W[K,J] ----------
// Block: 256 threads = 16(tx: cols) x 16(ty: rows); tile = 128 rows x J cols.
// INB_RELU: A-element is relu(A + inb[k]) (fuses layer-1 bias+relu into GEMM2).
template<int K, int J, bool INB_RELU>
__global__ __launch_bounds__(256)
void k_gemm(const float* __restrict__ A, const float* __restrict__ Wm,
            const float* __restrict__ inb, float* __restrict__ C, int n) {
    constexpr int KC = 16;
    constexpr int TM = 128;
    constexpr int JT = J / 16;                 // 4 (J=64) or 8 (J=128)

    __shared__ float As[KC][TM];
    __shared__ float Ws[KC][J];

    const int tid = threadIdx.x;
    const int tx  = tid & 15;
    const int ty  = tid >> 4;
    const int row0 = blockIdx.x * TM;

    float acc[8][JT];
#pragma unroll
    for (int i = 0; i < 8; i++)
#pragma unroll
        for (int j = 0; j < JT; j++) acc[i][j] = 0.0f;

    for (int kc0 = 0; kc0 < K; kc0 += KC) {
        // ---- load A tile: 128 rows x 16 k = 512 float4, 2 per thread
#pragma unroll
        for (int s = 0; s < 2; s++) {
            int u   = tid * 2 + s;             // 0..511
            int row = u >> 2;
            int f4  = (u & 3) * 4;
            float4 v = make_float4(0.f, 0.f, 0.f, 0.f);
            int gr = row0 + row;
            if (gr < n)
                v = *(const float4*)&A[(size_t)gr * K + kc0 + f4];
            if (INB_RELU) {
                const float* bb = &inb[kc0 + f4];
                v.x = fmaxf(v.x + bb[0], 0.f);
                v.y = fmaxf(v.y + bb[1], 0.f);
                v.z = fmaxf(v.z + bb[2], 0.f);
                v.w = fmaxf(v.w + bb[3], 0.f);
            }
            As[f4 + 0][row] = v.x;
            As[f4 + 1][row] = v.y;
            As[f4 + 2][row] = v.z;
            As[f4 + 3][row] = v.w;
        }
        // ---- load W tile: KC x J floats
        constexpr int WU = (KC * J / 4) / 256; // 1 or 2 float4 per thread
#pragma unroll
        for (int s = 0; s < WU; s++) {
            int u  = tid + s * 256;
            int k  = u / (J / 4);
            int jf = (u % (J / 4)) * 4;
            *(float4*)&Ws[k][jf] = *(const float4*)&Wm[(size_t)(kc0 + k) * J + jf];
        }
        __syncthreads();

        // ---- compute
#pragma unroll
        for (int k = 0; k < KC; k++) {
            float4 a0 = *(const float4*)&As[k][ty * 8];
            float4 a1 = *(const float4*)&As[k][ty * 8 + 4];
            float av[8] = {a0.x, a0.y, a0.z, a0.w, a1.x, a1.y, a1.z, a1.w};
            float wv[JT];
#pragma unroll
            for (int j4 = 0; j4 < JT / 4; j4++) {
                float4 wq = *(const float4*)&Ws[k][tx * JT + j4 * 4];
                wv[j4 * 4 + 0] = wq.x;
                wv[j4 * 4 + 1] = wq.y;
                wv[j4 * 4 + 2] = wq.z;
                wv[j4 * 4 + 3] = wq.w;
            }
#pragma unroll
            for (int i = 0; i < 8; i++)
#pragma unroll
                for (int j = 0; j < JT; j++)
                    acc[i][j] = fmaf(av[i], wv[j], acc[i][j]);
        }
        __syncthreads();
    }

    // ---- store
#pragma unroll
    for (int i = 0; i < 8; i++) {
        int gr = row0 + ty * 8 + i;
        if (gr < n) {
#pragma unroll
            for (int j4 = 0; j4 < JT / 4; j4++) {
                float4 v = make_float4(acc[i][j4 * 4 + 0], acc[i][j4 * 4 + 1],
                                       acc[i][j4 * 4 + 2], acc[i][j4 * 4 + 3]);
                *(float4*)&C[(size_t)gr * J + tx * JT + j4 * 4] = v;
            }
        }
    }
}

// ---------------- CSR aggregation: one warp per destination node ------------
// O[n] = H[n]*dinv[n]^2 + sum_{j in csr(n)} H[src[j]] * wt[j]   (+ bias)
// D=128: lane holds float4 (32*4).  D=64: lane holds float2 (32*2).
template<int D, bool BIAS>
__global__ __launch_bounds__(256)
void k_agg(const float* __restrict__ H, float* __restrict__ O,
           const float* __restrict__ b) {
    int warp = (blockIdx.x * blockDim.x + threadIdx.x) >> 5;
    if (warp >= NN) return;
    int lane = threadIdx.x & 31;
    constexpr int V = D / 32;                        // 4 or 2

    float acc[V];
    float s = g_dinv[warp]; s *= s;                  // self-loop coefficient

    const float* hn = &H[(size_t)warp * D + lane * V];
    if (V == 4) {
        float4 h = *(const float4*)hn;
        acc[0] = h.x * s; acc[1] = h.y * s; acc[2] = h.z * s; acc[3] = h.w * s;
    } else {
        float2 h = *(const float2*)hn;
        acc[0] = h.x * s; acc[1] = h.y * s;
    }

    int beg = g_rowstart[warp];
    int end = g_rowstart[warp + 1];
    for (int j = beg; j < end; j++) {
        int   r = __ldg(&g_src[j]);                  // broadcast across warp
        float w = __ldg(&g_wt[j]);
        const float* hr = &H[(size_t)r * D + lane * V];
        if (V == 4) {
            float4 h = *(const float4*)hr;
            acc[0] = fmaf(h.x, w, acc[0]);
            acc[1] = fmaf(h.y, w, acc[1]);
            acc[2] = fmaf(h.z, w, acc[2]);
            acc[3] = fmaf(h.w, w, acc[3]);
        } else {
            float2 h = *(const float2*)hr;
            acc[0] = fmaf(h.x, w, acc[0]);
            acc[1] = fmaf(h.y, w, acc[1]);
        }
    }

    float* on = &O[(size_t)warp * D + lane * V];
    if (V == 4) {
        float4 v;
        if (BIAS) {
            float4 bb = *(const float4*)&b[lane * 4];
            v = make_float4(acc[0] + bb.x, acc[1] + bb.y, acc[2] + bb.z, acc[3] + bb.w);
        } else {
            v = make_float4(acc[0], acc[1], acc[2], acc[3]);
        }
        *(float4*)on = v;
    } else {
        float2 v;
        if (BIAS) {
            float2 bb = *(const float2*)&b[lane * 2];
            v = make_float2(acc[0] + bb.x, acc[1] + bb.y);
        } else {
            v = make_float2(acc[0], acc[1]);
        }
        *(float2*)on = v;
    }
}

// ---------------- launch ------------------------------------------------------
extern "C" void kernel_launch(void* const* d_in, const int* in_sizes, int n_in,
                              void* d_out, int out_size) {
    const float* x  = (const float*)d_in[0];
    const void*  ei = d_in[1];                       // int32 or int64, autodetected
    const float* ew = (const float*)d_in[2];
    const float* W1 = (const float*)d_in[3];
    const float* b1 = (const float*)d_in[4];
    const float* W2 = (const float*)d_in[5];
    const float* b2 = (const float*)d_in[6];
    float*       out = (float*)d_out;

    float *p_h1, *p_agg1, *p_h2;
    cudaGetSymbolAddress((void**)&p_h1,   g_h1);
    cudaGetSymbolAddress((void**)&p_agg1, g_agg1);
    cudaGetSymbolAddress((void**)&p_h2,   g_h2);

    const int TB = 256;

    // ---- edge dtype detection + CSR preprocess
    k_detect <<<1, 1>>>((const unsigned int*)ei);
    k_init   <<<(NN + TB - 1) / TB, TB>>>();
    k_deg_cnt<<<(EE + TB - 1) / TB, TB>>>(ei, ew);
    k_dinv   <<<(NN + TB - 1) / TB, TB>>>();
    k_scan   <<<1, 1024>>>();
    k_fill   <<<(EE + TB - 1) / TB, TB>>>(ei, ew);

    // ---- layer 1: h1 = x @ W1 ; agg1 = A_hat @ h1   (no bias yet)
    k_gemm<IN_D, HID_D, false><<<(NN + 127) / 128, 256>>>(x, W1, nullptr, p_h1, NN);
    k_agg<HID_D, false><<<(NN * 32 + TB - 1) / TB, TB>>>(p_h1, p_agg1, nullptr);

    // ---- layer 2: h2 = relu(agg1 + b1) @ W2 ; out = A_hat @ h2 + b2
    k_gemm<HID_D, OUT_D, true><<<(NN + 127) / 128, 256>>>(p_agg1, W2, b1, p_h2, NN);
    k_agg<OUT_D, true><<<(NN * 32 + TB - 1) / TB, TB>>>(p_h2, out, b2);
}

// round 6
// speedup vs baseline: 1.0045x; 1.0045x over previous
#include <cuda_runtime.h>

#define NN 100000
#define EE 1600000
#define IN_D 128
#define HID_D 64
#define OUT_D 128

// ---------------- device scratch (globals: no allocation allowed) ----------
__device__ int   g_is64;              // 1 if edge_index is int64, 0 if int32
__device__ float g_deg [NN];
__device__ float g_dinv[NN];
__device__ int   g_cnt [NN];          // in-degree histogram (edges only)
__device__ int   g_rowstart[NN + 1];  // CSR offsets by destination
__device__ int   g_cursor[NN];        // fill cursors
__device__ int   g_src[EE];           // CSR: source node per edge
__device__ float g_wt [EE];           // CSR: normalized weight per edge
__device__ __align__(16) float g_h1  [(size_t)NN * HID_D];   // x @ W1
__device__ __align__(16) float g_agg1[(size_t)NN * HID_D];   // propagated layer-1
__device__ __align__(16) float g_h2  [(size_t)NN * OUT_D];   // relu(agg1+b1) @ W2

// ---------------- packed f32x2 helpers (sm_100+ FFMA2) ----------------------
__device__ __forceinline__ unsigned long long pack2(float x, float y) {
    unsigned long long r;
    asm("mov.b64 %0, {%1, %2};" : "=l"(r) : "f"(x), "f"(y));
    return r;
}
__device__ __forceinline__ void unpack2(unsigned long long p, float& x, float& y) {
    asm("mov.b64 {%0, %1}, %2;" : "=f"(x), "=f"(y) : "l"(p));
}
__device__ __forceinline__ void fma2(unsigned long long& d,
                                     unsigned long long a, unsigned long long b) {
    asm("fma.rn.f32x2 %0, %1, %2, %3;" : "=l"(d) : "l"(a), "l"(b), "l"(d));
}

// ---------------- edge dtype autodetect (1 warp, ballot) --------------------
// int64 LE: odd 32-bit words are the (zero) high halves. int32: odd words are
// random indices in [0,NN); 32 consecutive zeros has P ~ 1e-160.
__global__ void k_detect(const unsigned int* __restrict__ ew) {
    int lane = threadIdx.x;
    unsigned int v = ew[2 * lane + 1];
    unsigned int any = __ballot_sync(0xFFFFFFFFu, v != 0u);
    if (lane == 0) g_is64 = (any == 0u);
}

__device__ __forceinline__ int edge_row(const void* ei, int e) {
    if (g_is64) return (int)((const long long*)ei)[e];
    return ((const int*)ei)[e];
}
__device__ __forceinline__ int edge_col(const void* ei, int e) {
    if (g_is64) return (int)((const long long*)ei)[(size_t)EE + e];
    return ((const int*)ei)[(size_t)EE + e];
}

// ---------------- degree / histogram ----------------------------------------
__global__ void k_init() {
    int i = blockIdx.x * blockDim.x + threadIdx.x;
    if (i < NN) { g_deg[i] = 1.0f; g_cnt[i] = 0; }   // self-loop weight 1
}

__global__ void k_deg_cnt(const void* __restrict__ ei, const float* __restrict__ w) {
    int e = blockIdx.x * blockDim.x + threadIdx.x;
    if (e < EE) {
        int c = edge_col(ei, e);                     // col = destination
        atomicAdd(&g_deg[c], w[e]);                  // scalar float atomic
        atomicAdd(&g_cnt[c], 1);                     // scalar int atomic
    }
}

__global__ void k_dinv() {
    int i = blockIdx.x * blockDim.x + threadIdx.x;
    if (i < NN) g_dinv[i] = rsqrtf(g_deg[i]);        // deg >= 1 always
}

// ---------------- single-block chunked exclusive scan -----------------------
__global__ void k_scan() {                           // <<<1, 1024>>>
    const int T = 1024;
    int t = threadIdx.x;
    int chunk = (NN + T - 1) / T;                    // 98
    int lo = t * chunk;
    int hi = lo + chunk; if (hi > NN) hi = NN;

    int s = 0;
    for (int i = lo; i < hi; i++) s += g_cnt[i];

    __shared__ int ps[T];
    ps[t] = s;
    __syncthreads();
    for (int off = 1; off < T; off <<= 1) {          // inclusive scan
        int v = (t >= off) ? ps[t - off] : 0;
        __syncthreads();
        ps[t] += v;
        __syncthreads();
    }
    int base = (t > 0) ? ps[t - 1] : 0;              // exclusive base for chunk
    for (int i = lo; i < hi; i++) {
        int c = g_cnt[i];
        g_rowstart[i] = base;
        g_cursor[i]   = base;
        base += c;
    }
    if (t == T - 1) g_rowstart[NN] = ps[T - 1];      // == EE
}

// ---------------- CSR fill (dest-sorted) -------------------------------------
__global__ void k_fill(const void* __restrict__ ei, const float* __restrict__ w) {
    int e = blockIdx.x * blockDim.x + threadIdx.x;
    if (e >= EE) return;
    int r = edge_row(ei, e);
    int c = edge_col(ei, e);
    float nm = g_dinv[r] * w[e] * g_dinv[c];
    int pos = atomicAdd(&g_cursor[c], 1);            // scalar int atomic
    g_src[pos] = r;
    g_wt [pos] = nm;
}

// ---------------- register-tiled SGEMM with packed FFMA2 --------------------
// C[n,J] = f(A[n,K]) @ W[K,J]. Block 256 = 16(tx) x 16(ty); tile 128 x J.
// INB_RELU fuses relu(A + inb[k]) into the A-tile load (layer-2 input).
template<int K, int J, bool INB_RELU>
__global__ __launch_bounds__(256)
void k_gemm(const float* __restrict__ A, const float* __restrict__ Wm,
            const float* __restrict__ inb, float* __restrict__ C, int n) {
    constexpr int KC = 16;
    constexpr int TM = 128;
    constexpr int JT = J / 16;                 // 4 (J=64) or 8 (J=128)
    constexpr int JP = JT / 2;                 // f32x2 pairs per row

    __shared__ float As[KC][TM];
    __shared__ float Ws[KC][J];

    const int tid = threadIdx.x;
    const int tx  = tid & 15;
    const int ty  = tid >> 4;
    const int row0 = blockIdx.x * TM;

    unsigned long long acc[8][JP];
    const unsigned long long z = pack2(0.f, 0.f);
#pragma unroll
    for (int i = 0; i < 8; i++)
#pragma unroll
        for (int j = 0; j < JP; j++) acc[i][j] = z;

    for (int kc0 = 0; kc0 < K; kc0 += KC) {
        // ---- load A tile: 128 rows x 16 k = 512 float4, 2 per thread
#pragma unroll
        for (int s = 0; s < 2; s++) {
            int u   = tid * 2 + s;             // 0..511
            int row = u >> 2;
            int f4  = (u & 3) * 4;
            float4 v = make_float4(0.f, 0.f, 0.f, 0.f);
            int gr = row0 + row;
            if (gr < n)
                v = *(const float4*)&A[(size_t)gr * K + kc0 + f4];
            if (INB_RELU) {
                const float* bb = &inb[kc0 + f4];
                v.x = fmaxf(v.x + bb[0], 0.f);
                v.y = fmaxf(v.y + bb[1], 0.f);
                v.z = fmaxf(v.z + bb[2], 0.f);
                v.w = fmaxf(v.w + bb[3], 0.f);
            }
            As[f4 + 0][row] = v.x;
            As[f4 + 1][row] = v.y;
            As[f4 + 2][row] = v.z;
            As[f4 + 3][row] = v.w;
        }
        // ---- load W tile: KC x J floats
        constexpr int WU = (KC * J / 4) / 256; // 1 or 2 float4 per thread
#pragma unroll
        for (int s = 0; s < WU; s++) {
            int u  = tid + s * 256;
            int k  = u / (J / 4);
            int jf = (u % (J / 4)) * 4;
            *(float4*)&Ws[k][jf] = *(const float4*)&Wm[(size_t)(kc0 + k) * J + jf];
        }
        __syncthreads();

        // ---- compute (packed f32x2: 2 FMAs per FFMA2 issue)
#pragma unroll
        for (int k = 0; k < KC; k++) {
            float4 a0 = *(const float4*)&As[k][ty * 8];
            float4 a1 = *(const float4*)&As[k][ty * 8 + 4];
            unsigned long long ap[8];
            ap[0] = pack2(a0.x, a0.x); ap[1] = pack2(a0.y, a0.y);
            ap[2] = pack2(a0.z, a0.z); ap[3] = pack2(a0.w, a0.w);
            ap[4] = pack2(a1.x, a1.x); ap[5] = pack2(a1.y, a1.y);
            ap[6] = pack2(a1.z, a1.z); ap[7] = pack2(a1.w, a1.w);
            unsigned long long wp[JP];
#pragma unroll
            for (int j4 = 0; j4 < JT / 4; j4++) {
                float4 wq = *(const float4*)&Ws[k][tx * JT + j4 * 4];
                wp[j4 * 2 + 0] = pack2(wq.x, wq.y);
                wp[j4 * 2 + 1] = pack2(wq.z, wq.w);
            }
#pragma unroll
            for (int i = 0; i < 8; i++)
#pragma unroll
                for (int j = 0; j < JP; j++)
                    fma2(acc[i][j], ap[i], wp[j]);
        }
        __syncthreads();
    }

    // ---- store
#pragma unroll
    for (int i = 0; i < 8; i++) {
        int gr = row0 + ty * 8 + i;
        if (gr < n) {
#pragma unroll
            for (int j4 = 0; j4 < JT / 4; j4++) {
                float4 v;
                unpack2(acc[i][j4 * 2 + 0], v.x, v.y);
                unpack2(acc[i][j4 * 2 + 1], v.z, v.w);
                *(float4*)&C[(size_t)gr * J + tx * JT + j4 * 4] = v;
            }
        }
    }
}

// ---------------- CSR aggregation: one warp per destination node ------------
// O[n] = H[n]*dinv[n]^2 + sum_{j in csr(n)} H[src[j]] * wt[j]   (+ bias)
// Edge loop unrolled x4 with prefetched indices for MLP on the L2 gathers.
template<int D, bool BIAS>
__global__ __launch_bounds__(256)
void k_agg(const float* __restrict__ H, float* __restrict__ O,
           const float* __restrict__ b) {
    int warp = (blockIdx.x * blockDim.x + threadIdx.x) >> 5;
    if (warp >= NN) return;
    int lane = threadIdx.x & 31;
    constexpr int V = D / 32;                        // 4 or 2

    float acc[V];
    float s = g_dinv[warp]; s *= s;                  // self-loop coefficient

    const float* hn = &H[(size_t)warp * D + lane * V];
    if (V == 4) {
        float4 h = *(const float4*)hn;
        acc[0] = h.x * s; acc[1] = h.y * s; acc[2] = h.z * s; acc[3] = h.w * s;
    } else {
        float2 h = *(const float2*)hn;
        acc[0] = h.x * s; acc[1] = h.y * s;
    }

    int beg = g_rowstart[warp];
    int end = g_rowstart[warp + 1];
    int j = beg;

    for (; j + 4 <= end; j += 4) {
        int   r0 = __ldg(&g_src[j + 0]), r1 = __ldg(&g_src[j + 1]);
        int   r2 = __ldg(&g_src[j + 2]), r3 = __ldg(&g_src[j + 3]);
        float w0 = __ldg(&g_wt[j + 0]),  w1 = __ldg(&g_wt[j + 1]);
        float w2 = __ldg(&g_wt[j + 2]),  w3 = __ldg(&g_wt[j + 3]);
        if (V == 4) {
            float4 h0 = *(const float4*)&H[(size_t)r0 * D + lane * 4];
            float4 h1 = *(const float4*)&H[(size_t)r1 * D + lane * 4];
            float4 h2 = *(const float4*)&H[(size_t)r2 * D + lane * 4];
            float4 h3 = *(const float4*)&H[(size_t)r3 * D + lane * 4];
            acc[0] = fmaf(h0.x, w0, acc[0]); acc[1] = fmaf(h0.y, w0, acc[1]);
            acc[2] = fmaf(h0.z, w0, acc[2]); acc[3] = fmaf(h0.w, w0, acc[3]);
            acc[0] = fmaf(h1.x, w1, acc[0]); acc[1] = fmaf(h1.y, w1, acc[1]);
            acc[2] = fmaf(h1.z, w1, acc[2]); acc[3] = fmaf(h1.w, w1, acc[3]);
            acc[0] = fmaf(h2.x, w2, acc[0]); acc[1] = fmaf(h2.y, w2, acc[1]);
            acc[2] = fmaf(h2.z, w2, acc[2]); acc[3] = fmaf(h2.w, w2, acc[3]);
            acc[0] = fmaf(h3.x, w3, acc[0]); acc[1] = fmaf(h3.y, w3, acc[1]);
            acc[2] = fmaf(h3.z, w3, acc[2]); acc[3] = fmaf(h3.w, w3, acc[3]);
        } else {
            float2 h0 = *(const float2*)&H[(size_t)r0 * D + lane * 2];
            float2 h1 = *(const float2*)&H[(size_t)r1 * D + lane * 2];
            float2 h2 = *(const float2*)&H[(size_t)r2 * D + lane * 2];
            float2 h3 = *(const float2*)&H[(size_t)r3 * D + lane * 2];
            acc[0] = fmaf(h0.x, w0, acc[0]); acc[1] = fmaf(h0.y, w0, acc[1]);
            acc[0] = fmaf(h1.x, w1, acc[0]); acc[1] = fmaf(h1.y, w1, acc[1]);
            acc[0] = fmaf(h2.x, w2, acc[0]); acc[1] = fmaf(h2.y, w2, acc[1]);
            acc[0] = fmaf(h3.x, w3, acc[0]); acc[1] = fmaf(h3.y, w3, acc[1]);
        }
    }
    for (; j < end; j++) {
        int   r = __ldg(&g_src[j]);
        float w = __ldg(&g_wt[j]);
        const float* hr = &H[(size_t)r * D + lane * V];
        if (V == 4) {
            float4 h = *(const float4*)hr;
            acc[0] = fmaf(h.x, w, acc[0]); acc[1] = fmaf(h.y, w, acc[1]);
            acc[2] = fmaf(h.z, w, acc[2]); acc[3] = fmaf(h.w, w, acc[3]);
        } else {
            float2 h = *(const float2*)hr;
            acc[0] = fmaf(h.x, w, acc[0]); acc[1] = fmaf(h.y, w, acc[1]);
        }
    }

    float* on = &O[(size_t)warp * D + lane * V];
    if (V == 4) {
        float4 v;
        if (BIAS) {
            float4 bb = *(const float4*)&b[lane * 4];
            v = make_float4(acc[0] + bb.x, acc[1] + bb.y, acc[2] + bb.z, acc[3] + bb.w);
        } else {
            v = make_float4(acc[0], acc[1], acc[2], acc[3]);
        }
        *(float4*)on = v;
    } else {
        float2 v;
        if (BIAS) {
            float2 bb = *(const float2*)&b[lane * 2];
            v = make_float2(acc[0] + bb.x, acc[1] + bb.y);
        } else {
            v = make_float2(acc[0], acc[1]);
        }
        *(float2*)on = v;
    }
}

// ---------------- launch ------------------------------------------------------
extern "C" void kernel_launch(void* const* d_in, const int* in_sizes, int n_in,
                              void* d_out, int out_size) {
    const float* x  = (const float*)d_in[0];
    const void*  ei = d_in[1];                       // int32 or int64, autodetected
    const float* ew = (const float*)d_in[2];
    const float* W1 = (const float*)d_in[3];
    const float* b1 = (const float*)d_in[4];
    const float* W2 = (const float*)d_in[5];
    const float* b2 = (const float*)d_in[6];
    float*       out = (float*)d_out;

    float *p_h1, *p_agg1, *p_h2;
    cudaGetSymbolAddress((void**)&p_h1,   g_h1);
    cudaGetSymbolAddress((void**)&p_agg1, g_agg1);
    cudaGetSymbolAddress((void**)&p_h2,   g_h2);

    const int TB = 256;

    // ---- edge dtype detection + CSR preprocess
    k_detect <<<1, 32>>>((const unsigned int*)ei);
    k_init   <<<(NN + TB - 1) / TB, TB>>>();
    k_deg_cnt<<<(EE + TB - 1) / TB, TB>>>(ei, ew);
    k_dinv   <<<(NN + TB - 1) / TB, TB>>>();
    k_scan   <<<1, 1024>>>();
    k_fill   <<<(EE + TB - 1) / TB, TB>>>(ei, ew);

    // ---- layer 1: h1 = x @ W1 ; agg1 = A_hat @ h1   (no bias yet)
    k_gemm<IN_D, HID_D, false><<<(NN + 127) / 128, 256>>>(x, W1, nullptr, p_h1, NN);
    k_agg<HID_D, false><<<(NN * 32 + TB - 1) / TB, TB>>>(p_h1, p_agg1, nullptr);

    // ---- layer 2: h2 = relu(agg1 + b1) @ W2 ; out = A_hat @ h2 + b2
    k_gemm<HID_D, OUT_D, true><<<(NN + 127) / 128, 256>>>(p_agg1, W2, b1, p_h2, NN);
    k_agg<OUT_D, true><<<(NN * 32 + TB - 1) / TB, TB>>>(p_h2, out, b2);
}